// round 12
// baseline (speedup 1.0000x reference)
#include <cuda_runtime.h>
#include <cstddef>

// Problem constants (fixed by the reference: N=1024, D=16, E=16384)
#define NNODES 1024
#define D_DIM  16
#define NM     16384          // N * D

// ---------------- scratch (device globals: allocation-free) ----------------
__device__ float g_diag[(size_t)NNODES * 256];  // 1.0 MB: dinv^2-scaled Gram sums
__device__ int   g_cnt [NNODES];                // 4 KB: per-node arrival counters

// Inline edge_index dtype probe (deterministic single word):
// int32 layout (2,32768): word 32769 = edge_index[1][1] = col[1] >= 1 (r < c).
// int64 LE layout: word 32769 = high half of edge_index[0][16384] < 1024 -> 0.
__device__ __forceinline__ int idx_stride(const int* eidx32) {
    return (__ldg(&eidx32[32769]) != 0) ? 1 : 2;
}

// Vector reduction into the compact L2-resident scratch. sm_90+ PTX.
__device__ __forceinline__ void red_add_v4(float* ptr, float a, float b,
                                           float c, float d) {
    asm volatile("red.global.add.v4.f32 [%0], {%1, %2, %3, %4};"
                 :: "l"(ptr), "f"(a), "f"(b), "f"(c), "f"(d) : "memory");
}

// Last-arriving warp for `node` copies its finished 1 KB Gram block from
// g_diag into out's diagonal block (r,r). Called only after the acquire fence.
__device__ __forceinline__ void flush_diag_block(float* __restrict__ out,
                                                 int node, int lane) {
    #pragma unroll
    for (int m = 0; m < 2; ++m) {
        const int f = lane + m * 32;            // float4 id 0..63 within block
        const int j = f >> 2;
        const int q = f & 3;
        const float4 v = *(const float4*)&g_diag[(size_t)node * 256 + f * 4];
        *(float4*)&out[(size_t)(node * 16 + j) * NM + node * 16 + q * 4] = v;
    }
}

// Fused pass: ONE WARP PER EDGE (8 edges per 256-thread CTA). Thread
// (j = lane>>2, q = lane&3) owns rows {j, j+8} x cols [4q, 4q+4) of
// T = A^T B, G1 = A^T A, G2 = B^T B: 6 LDS feed 24 FMAs per i-step.
//   - triu block (r,c): direct float4 stores from registers
//   - tril block (c,r): transpose through padded smem
//   - diag Gram: red.v4 into g_diag; threadfence-reduction counters per node,
//     the last-arriving warp flushes the completed diag block into `out`
//     (eliminates the separate flush kernel, R11's 8.9us launch+latency sink)
__global__ void __launch_bounds__(256) edge_fused_kernel(
        const float* __restrict__ degrees,
        const float* __restrict__ maps,
        const int*   __restrict__ eidx32,
        float*       __restrict__ out,
        int E) {
    __shared__ float Asm[8][256];
    __shared__ float Bsm[8][256];
    __shared__ float Tsm[8][16][20];   // pad 20: float4-aligned rows

    const int tid  = threadIdx.x;
    const int w    = tid >> 5;         // edge slot 0..7 (one warp each)
    const int lane = tid & 31;
    const int e    = blockIdx.x * 8 + w;

    const int stride = idx_stride(eidx32);
    const int r = eidx32[(size_t)e * stride];
    const int c = eidx32[(size_t)(2 * E + e) * stride];

    // Stage both maps: 64 float4 per matrix, 2 per lane
    {
        const float4* ga = (const float4*)(maps + (size_t)e * 256);
        const float4* gb = (const float4*)(maps + ((size_t)e + E) * 256);
        ((float4*)Asm[w])[lane]      = ga[lane];
        ((float4*)Asm[w])[lane + 32] = ga[lane + 32];
        ((float4*)Bsm[w])[lane]      = gb[lane];
        ((float4*)Bsm[w])[lane + 32] = gb[lane + 32];
    }
    __syncwarp();

    const int j = lane >> 2;           // row pair {j, j+8}, j in 0..7
    const int q = lane & 3;            // float4 column group 0..3

    float t00=0.f,t01=0.f,t02=0.f,t03=0.f, t10=0.f,t11=0.f,t12=0.f,t13=0.f;
    float p00=0.f,p01=0.f,p02=0.f,p03=0.f, p10=0.f,p11=0.f,p12=0.f,p13=0.f;
    float u00=0.f,u01=0.f,u02=0.f,u03=0.f, u10=0.f,u11=0.f,u12=0.f,u13=0.f;

    #pragma unroll
    for (int i = 0; i < 16; ++i) {
        const float  aj0 = Asm[w][i * 16 + j];         // broadcast
        const float  aj1 = Asm[w][i * 16 + j + 8];
        const float  bj0 = Bsm[w][i * 16 + j];
        const float  bj1 = Bsm[w][i * 16 + j + 8];
        const float4 a4  = *(const float4*)&Asm[w][i * 16 + q * 4];
        const float4 b4  = *(const float4*)&Bsm[w][i * 16 + q * 4];

        t00 += aj0*b4.x; t01 += aj0*b4.y; t02 += aj0*b4.z; t03 += aj0*b4.w;
        t10 += aj1*b4.x; t11 += aj1*b4.y; t12 += aj1*b4.z; t13 += aj1*b4.w;
        p00 += aj0*a4.x; p01 += aj0*a4.y; p02 += aj0*a4.z; p03 += aj0*a4.w;
        p10 += aj1*a4.x; p11 += aj1*a4.y; p12 += aj1*a4.z; p13 += aj1*a4.w;
        u00 += bj0*b4.x; u01 += bj0*b4.y; u02 += bj0*b4.z; u03 += bj0*b4.w;
        u10 += bj1*b4.x; u11 += bj1*b4.y; u12 += bj1*b4.z; u13 += bj1*b4.w;
    }

    const float dr = rsqrtf(degrees[r] * (float)D_DIM + 1.0f);
    const float dc = rsqrtf(degrees[c] * (float)D_DIM + 1.0f);
    const float s  = -(dr * dc);
    const float sr = dr * dr;
    const float sc = dc * dc;

    // Diagonal Gram contributions: 4 vector REDs per thread
    red_add_v4(&g_diag[(size_t)r * 256 + j * 16 + q * 4],
               sr * p00, sr * p01, sr * p02, sr * p03);
    red_add_v4(&g_diag[(size_t)r * 256 + (j + 8) * 16 + q * 4],
               sr * p10, sr * p11, sr * p12, sr * p13);
    red_add_v4(&g_diag[(size_t)c * 256 + j * 16 + q * 4],
               sc * u00, sc * u01, sc * u02, sc * u03);
    red_add_v4(&g_diag[(size_t)c * 256 + (j + 8) * 16 + q * 4],
               sc * u10, sc * u11, sc * u12, sc * u13);

    // Triu block (r,c): straight from registers, coalesced float4
    float4 v0;  v0.x = s*t00;  v0.y = s*t01;  v0.z = s*t02;  v0.w = s*t03;
    float4 v1;  v1.x = s*t10;  v1.y = s*t11;  v1.z = s*t12;  v1.w = s*t13;
    *(float4*)&out[(size_t)(r * 16 + j)     * NM + c * 16 + q * 4] = v0;
    *(float4*)&out[(size_t)(r * 16 + j + 8) * NM + c * 16 + q * 4] = v1;

    // Tril block (c,r) = T^T: stage, warp-sync, transpose-read, float4 store
    *(float4*)&Tsm[w][j][q * 4]     = v0;
    *(float4*)&Tsm[w][j + 8][q * 4] = v1;
    __syncwarp();
    float4 w0, w1;
    w0.x = Tsm[w][q*4+0][j];     w0.y = Tsm[w][q*4+1][j];
    w0.z = Tsm[w][q*4+2][j];     w0.w = Tsm[w][q*4+3][j];
    w1.x = Tsm[w][q*4+0][j+8];   w1.y = Tsm[w][q*4+1][j+8];
    w1.z = Tsm[w][q*4+2][j+8];   w1.w = Tsm[w][q*4+3][j+8];
    *(float4*)&out[(size_t)(c * 16 + j)     * NM + r * 16 + q * 4] = w0;
    *(float4*)&out[(size_t)(c * 16 + j + 8) * NM + r * 16 + q * 4] = w1;

    // ---- threadfence-reduction: last warp per node flushes its diag block ----
    // Release: make this warp's REDs globally visible, then count the arrival.
    __threadfence();
    __syncwarp();
    int last_r = 0, last_c = 0;
    if (lane == 0) {
        const int deg_r = (int)(degrees[r] + 0.5f);
        const int deg_c = (int)(degrees[c] + 0.5f);
        last_r = (atomicAdd(&g_cnt[r], 1) == deg_r - 1);
        last_c = (atomicAdd(&g_cnt[c], 1) == deg_c - 1);
    }
    last_r = __shfl_sync(0xffffffffu, last_r, 0);
    last_c = __shfl_sync(0xffffffffu, last_c, 0);

    if (last_r | last_c) {
        __threadfence();               // acquire: observe all other warps' REDs
        if (last_r) flush_diag_block(out, r, lane);
        if (last_c) flush_diag_block(out, c, lane);
    }
}

extern "C" void kernel_launch(void* const* d_in, const int* in_sizes, int n_in,
                              void* d_out, int out_size) {
    // Inputs (metadata order): adj_mat [N*N f32], degrees [N f32],
    // maps [2E*16*16 f32], edge_index [2*2E int]
    const float* degrees = (const float*)d_in[1];
    const float* maps    = (const float*)d_in[2];
    const int*   eidx32  = (const int*)d_in[3];
    float*       out     = (float*)d_out;

    const int E = in_sizes[2] / (2 * 256);   // maps has 2E blocks of 256 floats

    void* diag_ptr = nullptr;
    void* cnt_ptr  = nullptr;
    cudaGetSymbolAddress(&diag_ptr, g_diag);
    cudaGetSymbolAddress(&cnt_ptr,  g_cnt);

    // 1) Zero the scratch (1 MB Gram sums + 4 KB counters), then the 1.07 GB
    //    output (pure & serial: R5/R6 showed overlap is net-negative)
    cudaMemsetAsync(diag_ptr, 0, (size_t)NNODES * 256 * sizeof(float), 0);
    cudaMemsetAsync(cnt_ptr,  0, NNODES * sizeof(int), 0);
    cudaMemsetAsync(d_out, 0, (size_t)out_size * sizeof(float), 0);

    // 2) Fused: warp-per-edge compute + direct triu/tril stores + v4-REDs
    //    + last-arriver diagonal flush (no separate flush kernel)
    edge_fused_kernel<<<E / 8, 256>>>(degrees, maps, eidx32, out, E);
}

// round 13
// speedup vs baseline: 1.0711x; 1.0711x over previous
#include <cuda_runtime.h>
#include <cstddef>

// Problem constants (fixed by the reference: N=1024, D=16, E=16384)
#define NNODES 1024
#define D_DIM  16
#define NM     16384          // N * D

// ---------------- scratch (device global: allocation-free) -----------------
__device__ float g_diag[(size_t)NNODES * 256];  // 1.0 MB: dinv^2-scaled Gram sums

// Inline edge_index dtype probe (deterministic single word):
// int32 layout (2,32768): word 32769 = edge_index[1][1] = col[1] >= 1 (r < c).
// int64 LE layout: word 32769 = high half of edge_index[0][16384] < 1024 -> 0.
__device__ __forceinline__ int idx_stride(const int* eidx32) {
    return (__ldg(&eidx32[32769]) != 0) ? 1 : 2;
}

// Vector reduction into the compact L2-resident scratch (cheap address
// locality: each node's block is 1 KB contiguous). sm_90+ PTX.
__device__ __forceinline__ void red_add_v4(float* ptr, float a, float b,
                                           float c, float d) {
    asm volatile("red.global.add.v4.f32 [%0], {%1, %2, %3, %4};"
                 :: "l"(ptr), "f"(a), "f"(b), "f"(c), "f"(d) : "memory");
}

// Fused pass: ONE WARP PER EDGE (8 edges per 256-thread CTA). Thread
// (j = lane>>2, q = lane&3) owns rows {j, j+8} x cols [4q, 4q+4) of
// T = A^T B, G1 = A^T A, G2 = B^T B: 6 LDS feed 24 FMAs per i-step.
// All sharing is intra-warp -> __syncwarp only, no CTA barriers, NO fences
// (R12 showed per-warp __threadfence doubles this kernel's duration).
//   - triu block (r,c): direct float4 stores from registers
//   - tril block (c,r): transpose through padded smem (float4-aligned pad 20)
//   - diag Gram: red.v4 into g_diag (L2-resident; R8 showed direct-to-out
//     scattered atomics cost +17us)
__global__ void __launch_bounds__(256) edge_fused_kernel(
        const float* __restrict__ degrees,
        const float* __restrict__ maps,
        const int*   __restrict__ eidx32,
        float*       __restrict__ out,
        int E) {
    __shared__ float Asm[8][256];
    __shared__ float Bsm[8][256];
    __shared__ float Tsm[8][16][20];   // pad 20: float4-aligned rows

    const int tid  = threadIdx.x;
    const int w    = tid >> 5;         // edge slot 0..7 (one warp each)
    const int lane = tid & 31;
    const int e    = blockIdx.x * 8 + w;

    const int stride = idx_stride(eidx32);
    const int r = eidx32[(size_t)e * stride];
    const int c = eidx32[(size_t)(2 * E + e) * stride];

    // Stage both maps: 64 float4 per matrix, 2 per lane
    {
        const float4* ga = (const float4*)(maps + (size_t)e * 256);
        const float4* gb = (const float4*)(maps + ((size_t)e + E) * 256);
        ((float4*)Asm[w])[lane]      = ga[lane];
        ((float4*)Asm[w])[lane + 32] = ga[lane + 32];
        ((float4*)Bsm[w])[lane]      = gb[lane];
        ((float4*)Bsm[w])[lane + 32] = gb[lane + 32];
    }
    __syncwarp();

    const int j = lane >> 2;           // row pair {j, j+8}, j in 0..7
    const int q = lane & 3;            // float4 column group 0..3

    float t00=0.f,t01=0.f,t02=0.f,t03=0.f, t10=0.f,t11=0.f,t12=0.f,t13=0.f;
    float p00=0.f,p01=0.f,p02=0.f,p03=0.f, p10=0.f,p11=0.f,p12=0.f,p13=0.f;
    float u00=0.f,u01=0.f,u02=0.f,u03=0.f, u10=0.f,u11=0.f,u12=0.f,u13=0.f;

    #pragma unroll
    for (int i = 0; i < 16; ++i) {
        const float  aj0 = Asm[w][i * 16 + j];         // broadcast
        const float  aj1 = Asm[w][i * 16 + j + 8];
        const float  bj0 = Bsm[w][i * 16 + j];
        const float  bj1 = Bsm[w][i * 16 + j + 8];
        const float4 a4  = *(const float4*)&Asm[w][i * 16 + q * 4];
        const float4 b4  = *(const float4*)&Bsm[w][i * 16 + q * 4];

        t00 += aj0*b4.x; t01 += aj0*b4.y; t02 += aj0*b4.z; t03 += aj0*b4.w;
        t10 += aj1*b4.x; t11 += aj1*b4.y; t12 += aj1*b4.z; t13 += aj1*b4.w;
        p00 += aj0*a4.x; p01 += aj0*a4.y; p02 += aj0*a4.z; p03 += aj0*a4.w;
        p10 += aj1*a4.x; p11 += aj1*a4.y; p12 += aj1*a4.z; p13 += aj1*a4.w;
        u00 += bj0*b4.x; u01 += bj0*b4.y; u02 += bj0*b4.z; u03 += bj0*b4.w;
        u10 += bj1*b4.x; u11 += bj1*b4.y; u12 += bj1*b4.z; u13 += bj1*b4.w;
    }

    const float dr = rsqrtf(degrees[r] * (float)D_DIM + 1.0f);
    const float dc = rsqrtf(degrees[c] * (float)D_DIM + 1.0f);
    const float s  = -(dr * dc);
    const float sr = dr * dr;
    const float sc = dc * dc;

    // Diagonal Gram contributions: 4 vector REDs per thread
    red_add_v4(&g_diag[(size_t)r * 256 + j * 16 + q * 4],
               sr * p00, sr * p01, sr * p02, sr * p03);
    red_add_v4(&g_diag[(size_t)r * 256 + (j + 8) * 16 + q * 4],
               sr * p10, sr * p11, sr * p12, sr * p13);
    red_add_v4(&g_diag[(size_t)c * 256 + j * 16 + q * 4],
               sc * u00, sc * u01, sc * u02, sc * u03);
    red_add_v4(&g_diag[(size_t)c * 256 + (j + 8) * 16 + q * 4],
               sc * u10, sc * u11, sc * u12, sc * u13);

    // Triu block (r,c): straight from registers, coalesced float4
    float4 v0;  v0.x = s*t00;  v0.y = s*t01;  v0.z = s*t02;  v0.w = s*t03;
    float4 v1;  v1.x = s*t10;  v1.y = s*t11;  v1.z = s*t12;  v1.w = s*t13;
    *(float4*)&out[(size_t)(r * 16 + j)     * NM + c * 16 + q * 4] = v0;
    *(float4*)&out[(size_t)(r * 16 + j + 8) * NM + c * 16 + q * 4] = v1;

    // Tril block (c,r) = T^T: stage, warp-sync, transpose-read, float4 store
    *(float4*)&Tsm[w][j][q * 4]     = v0;
    *(float4*)&Tsm[w][j + 8][q * 4] = v1;
    __syncwarp();
    float4 w0, w1;
    w0.x = Tsm[w][q*4+0][j];     w0.y = Tsm[w][q*4+1][j];
    w0.z = Tsm[w][q*4+2][j];     w0.w = Tsm[w][q*4+3][j];
    w1.x = Tsm[w][q*4+0][j+8];   w1.y = Tsm[w][q*4+1][j+8];
    w1.z = Tsm[w][q*4+2][j+8];   w1.w = Tsm[w][q*4+3][j+8];
    *(float4*)&out[(size_t)(c * 16 + j)     * NM + r * 16 + q * 4] = w0;
    *(float4*)&out[(size_t)(c * 16 + j + 8) * NM + r * 16 + q * 4] = w1;
}

// Diag flush: 32 CTAs x 256 threads, MLP=8. Each thread copies 8 independent
// float4s (8192 float4s apart): long independent latency chains, 8 warps/CTA
// for per-SM overlap (R10's 64x256/MLP4 measured 5.1us vs 8.9us at 128x128).
__global__ void __launch_bounds__(256) inject_diag_kernel(float* __restrict__ out) {
    const int f0 = blockIdx.x * 256 + threadIdx.x;   // float4 id 0..8191

    float4 v[8];
    #pragma unroll
    for (int m = 0; m < 8; ++m)
        v[m] = *(const float4*)&g_diag[(size_t)(f0 + m * 8192) * 4];

    #pragma unroll
    for (int m = 0; m < 8; ++m) {
        const int f    = f0 + m * 8192;
        const int node = f >> 6;         // 64 float4 per 16x16 block
        const int rem  = f & 63;
        const int j    = rem >> 2;
        const int q    = rem & 3;
        *(float4*)&out[(size_t)(node * 16 + j) * NM + node * 16 + q * 4] = v[m];
    }
}

extern "C" void kernel_launch(void* const* d_in, const int* in_sizes, int n_in,
                              void* d_out, int out_size) {
    // Inputs (metadata order): adj_mat [N*N f32], degrees [N f32],
    // maps [2E*16*16 f32], edge_index [2*2E int]
    const float* degrees = (const float*)d_in[1];
    const float* maps    = (const float*)d_in[2];
    const int*   eidx32  = (const int*)d_in[3];
    float*       out     = (float*)d_out;

    const int E = in_sizes[2] / (2 * 256);   // maps has 2E blocks of 256 floats

    void* diag_ptr = nullptr;
    cudaGetSymbolAddress(&diag_ptr, g_diag);

    // 1) Zero the 1 MB diag scratch, then the 1.07 GB output (pure & serial:
    //    R5/R6 showed overlap with the big memset is net-negative)
    cudaMemsetAsync(diag_ptr, 0, (size_t)NNODES * 256 * sizeof(float), 0);
    cudaMemsetAsync(d_out, 0, (size_t)out_size * sizeof(float), 0);

    // 2) Fused: warp-per-edge compute + direct triu/tril stores + v4-REDs
    edge_fused_kernel<<<E / 8, 256>>>(degrees, maps, eidx32, out, E);

    // 3) Flush the accumulated diagonal blocks (2 MB, MLP-8, 32 CTAs x 256)
    inject_diag_kernel<<<32, 256>>>(out);
}

// round 14
// speedup vs baseline: 1.0730x; 1.0017x over previous
#include <cuda_runtime.h>
#include <cstddef>

// Problem constants (fixed by the reference: N=1024, D=16, E=16384)
#define NNODES 1024
#define D_DIM  16
#define NM     16384          // N * D

// ---------------- scratch (device global: allocation-free) -----------------
__device__ float g_diag[(size_t)NNODES * 256];  // 1.0 MB: dinv^2-scaled Gram sums

// Inline edge_index dtype probe (deterministic single word):
// int32 layout (2,32768): word 32769 = edge_index[1][1] = col[1] >= 1 (r < c).
// int64 LE layout: word 32769 = high half of edge_index[0][16384] < 1024 -> 0.
__device__ __forceinline__ int idx_stride(const int* eidx32) {
    return (__ldg(&eidx32[32769]) != 0) ? 1 : 2;
}

// Vector reduction into the compact L2-resident scratch (cheap address
// locality: each node's block is 1 KB contiguous). sm_90+ PTX.
__device__ __forceinline__ void red_add_v4(float* ptr, float a, float b,
                                           float c, float d) {
    asm volatile("red.global.add.v4.f32 [%0], {%1, %2, %3, %4};"
                 :: "l"(ptr), "f"(a), "f"(b), "f"(c), "f"(d) : "memory");
}

// Fused pass: ONE WARP PER EDGE (8 edges per 256-thread CTA). Thread
// (j = lane>>2, q = lane&3) owns rows {j, j+8} x cols [4q, 4q+4) of
// T = A^T B, G1 = A^T A, G2 = B^T B: 6 LDS feed 24 FMAs per i-step.
// All sharing is intra-warp -> __syncwarp only, no CTA barriers, NO fences
// (R12: per-warp __threadfence doubled this kernel's duration).
//   - triu block (r,c): direct float4 stores from registers
//   - tril block (c,r): transpose through padded smem (float4-aligned pad 20)
//   - diag Gram: red.v4 into g_diag (L2-resident; R8: direct-to-out
//     scattered atomics cost +17us)
__global__ void __launch_bounds__(256) edge_fused_kernel(
        const float* __restrict__ degrees,
        const float* __restrict__ maps,
        const int*   __restrict__ eidx32,
        float*       __restrict__ out,
        int E) {
    __shared__ float Asm[8][256];
    __shared__ float Bsm[8][256];
    __shared__ float Tsm[8][16][20];   // pad 20: float4-aligned rows

    const int tid  = threadIdx.x;
    const int w    = tid >> 5;         // edge slot 0..7 (one warp each)
    const int lane = tid & 31;
    const int e    = blockIdx.x * 8 + w;

    const int stride = idx_stride(eidx32);
    const int r = eidx32[(size_t)e * stride];
    const int c = eidx32[(size_t)(2 * E + e) * stride];

    // Stage both maps: 64 float4 per matrix, 2 per lane
    {
        const float4* ga = (const float4*)(maps + (size_t)e * 256);
        const float4* gb = (const float4*)(maps + ((size_t)e + E) * 256);
        ((float4*)Asm[w])[lane]      = ga[lane];
        ((float4*)Asm[w])[lane + 32] = ga[lane + 32];
        ((float4*)Bsm[w])[lane]      = gb[lane];
        ((float4*)Bsm[w])[lane + 32] = gb[lane + 32];
    }
    __syncwarp();

    const int j = lane >> 2;           // row pair {j, j+8}, j in 0..7
    const int q = lane & 3;            // float4 column group 0..3

    float t00=0.f,t01=0.f,t02=0.f,t03=0.f, t10=0.f,t11=0.f,t12=0.f,t13=0.f;
    float p00=0.f,p01=0.f,p02=0.f,p03=0.f, p10=0.f,p11=0.f,p12=0.f,p13=0.f;
    float u00=0.f,u01=0.f,u02=0.f,u03=0.f, u10=0.f,u11=0.f,u12=0.f,u13=0.f;

    #pragma unroll
    for (int i = 0; i < 16; ++i) {
        const float  aj0 = Asm[w][i * 16 + j];         // broadcast
        const float  aj1 = Asm[w][i * 16 + j + 8];
        const float  bj0 = Bsm[w][i * 16 + j];
        const float  bj1 = Bsm[w][i * 16 + j + 8];
        const float4 a4  = *(const float4*)&Asm[w][i * 16 + q * 4];
        const float4 b4  = *(const float4*)&Bsm[w][i * 16 + q * 4];

        t00 += aj0*b4.x; t01 += aj0*b4.y; t02 += aj0*b4.z; t03 += aj0*b4.w;
        t10 += aj1*b4.x; t11 += aj1*b4.y; t12 += aj1*b4.z; t13 += aj1*b4.w;
        p00 += aj0*a4.x; p01 += aj0*a4.y; p02 += aj0*a4.z; p03 += aj0*a4.w;
        p10 += aj1*a4.x; p11 += aj1*a4.y; p12 += aj1*a4.z; p13 += aj1*a4.w;
        u00 += bj0*b4.x; u01 += bj0*b4.y; u02 += bj0*b4.z; u03 += bj0*b4.w;
        u10 += bj1*b4.x; u11 += bj1*b4.y; u12 += bj1*b4.z; u13 += bj1*b4.w;
    }

    const float dr = rsqrtf(degrees[r] * (float)D_DIM + 1.0f);
    const float dc = rsqrtf(degrees[c] * (float)D_DIM + 1.0f);
    const float s  = -(dr * dc);
    const float sr = dr * dr;
    const float sc = dc * dc;

    // Diagonal Gram contributions: 4 vector REDs per thread
    red_add_v4(&g_diag[(size_t)r * 256 + j * 16 + q * 4],
               sr * p00, sr * p01, sr * p02, sr * p03);
    red_add_v4(&g_diag[(size_t)r * 256 + (j + 8) * 16 + q * 4],
               sr * p10, sr * p11, sr * p12, sr * p13);
    red_add_v4(&g_diag[(size_t)c * 256 + j * 16 + q * 4],
               sc * u00, sc * u01, sc * u02, sc * u03);
    red_add_v4(&g_diag[(size_t)c * 256 + (j + 8) * 16 + q * 4],
               sc * u10, sc * u11, sc * u12, sc * u13);

    // Triu block (r,c): straight from registers, coalesced float4
    float4 v0;  v0.x = s*t00;  v0.y = s*t01;  v0.z = s*t02;  v0.w = s*t03;
    float4 v1;  v1.x = s*t10;  v1.y = s*t11;  v1.z = s*t12;  v1.w = s*t13;
    *(float4*)&out[(size_t)(r * 16 + j)     * NM + c * 16 + q * 4] = v0;
    *(float4*)&out[(size_t)(r * 16 + j + 8) * NM + c * 16 + q * 4] = v1;

    // Tril block (c,r) = T^T: stage, warp-sync, transpose-read, float4 store
    *(float4*)&Tsm[w][j][q * 4]     = v0;
    *(float4*)&Tsm[w][j + 8][q * 4] = v1;
    __syncwarp();
    float4 w0, w1;
    w0.x = Tsm[w][q*4+0][j];     w0.y = Tsm[w][q*4+1][j];
    w0.z = Tsm[w][q*4+2][j];     w0.w = Tsm[w][q*4+3][j];
    w1.x = Tsm[w][q*4+0][j+8];   w1.y = Tsm[w][q*4+1][j+8];
    w1.z = Tsm[w][q*4+2][j+8];   w1.w = Tsm[w][q*4+3][j+8];
    *(float4*)&out[(size_t)(c * 16 + j)     * NM + r * 16 + q * 4] = w0;
    *(float4*)&out[(size_t)(c * 16 + j + 8) * NM + r * 16 + q * 4] = w1;
}

// Diag flush: EXACT R10 configuration (measured 5.1us — the best of the four
// tested shapes): 64 CTAs x 256 threads, MLP=4, each thread copies 4
// independent float4s spaced 16384 float4s apart.
__global__ void __launch_bounds__(256) inject_diag_kernel(float* __restrict__ out) {
    const int f0 = blockIdx.x * blockDim.x + threadIdx.x;   // float4 id 0..16383

    float4 v[4];
    #pragma unroll
    for (int m = 0; m < 4; ++m)
        v[m] = *(const float4*)&g_diag[(size_t)(f0 + m * 16384) * 4];

    #pragma unroll
    for (int m = 0; m < 4; ++m) {
        const int f    = f0 + m * 16384;
        const int node = f >> 6;         // 64 float4 per 16x16 block
        const int rem  = f & 63;
        const int j    = rem >> 2;
        const int q    = rem & 3;
        *(float4*)&out[(size_t)(node * 16 + j) * NM + node * 16 + q * 4] = v[m];
    }
}

extern "C" void kernel_launch(void* const* d_in, const int* in_sizes, int n_in,
                              void* d_out, int out_size) {
    // Inputs (metadata order): adj_mat [N*N f32], degrees [N f32],
    // maps [2E*16*16 f32], edge_index [2*2E int]
    const float* degrees = (const float*)d_in[1];
    const float* maps    = (const float*)d_in[2];
    const int*   eidx32  = (const int*)d_in[3];
    float*       out     = (float*)d_out;

    const int E = in_sizes[2] / (2 * 256);   // maps has 2E blocks of 256 floats

    void* diag_ptr = nullptr;
    cudaGetSymbolAddress(&diag_ptr, g_diag);

    // 1) Zero the 1 MB diag scratch, then the 1.07 GB output (pure & serial:
    //    R5/R6 showed overlap with the big memset is net-negative)
    cudaMemsetAsync(diag_ptr, 0, (size_t)NNODES * 256 * sizeof(float), 0);
    cudaMemsetAsync(d_out, 0, (size_t)out_size * sizeof(float), 0);

    // 2) Fused: warp-per-edge compute + direct triu/tril stores + v4-REDs
    edge_fused_kernel<<<E / 8, 256>>>(degrees, maps, eidx32, out, E);

    // 3) Flush the accumulated diagonal blocks (2 MB, 64 CTAs x 256, MLP4)
    inject_diag_kernel<<<64, 256>>>(out);
}

// round 15
// speedup vs baseline: 1.0921x; 1.0178x over previous
#include <cuda_runtime.h>
#include <cstddef>

// Problem constants (fixed by the reference: N=1024, D=16, E=16384)
#define NNODES 1024
#define D_DIM  16
#define NM     16384          // N * D

// Inline edge_index dtype probe (deterministic single word):
// int32 layout (2,32768): word 32769 = edge_index[1][1] = col[1] >= 1 (r < c).
// int64 LE layout: word 32769 = high half of edge_index[0][16384] < 1024 -> 0.
__device__ __forceinline__ int idx_stride(const int* eidx32) {
    return (__ldg(&eidx32[32769]) != 0) ? 1 : 2;
}

// Vector reduction (sm_90+ PTX): one instruction per 16B of accumulation.
__device__ __forceinline__ void red_add_v4(float* ptr, float a, float b,
                                           float c, float d) {
    asm volatile("red.global.add.v4.f32 [%0], {%1, %2, %3, %4};"
                 :: "l"(ptr), "f"(a), "f"(b), "f"(c), "f"(d) : "memory");
}

// Fused pass: ONE WARP PER EDGE (8 edges per 256-thread CTA). Thread
// (j = lane>>2, q = lane&3) owns rows {j, j+8} x cols [4q, 4q+4) of
// T = A^T B, G1 = A^T A, G2 = B^T B: 6 LDS feed 24 FMAs per i-step.
// All sharing is intra-warp -> __syncwarp only, no CTA barriers, NO fences
// (R12: per-warp __threadfence doubled this kernel's duration).
//   - triu block (r,c): direct float4 stores from registers
//   - tril block (c,r): transpose through padded smem (float4-aligned pad 20)
//   - diag Gram: red.v4 DIRECTLY into out's diagonal blocks (memset provides
//     the zero initial value). This deletes the scratch buffer, its memset,
//     and the ~8.5us flush kernel. R8's +17us penalty for out-targeted
//     atomics was measured with 4x more RED ops (8.4M scalar vs 2.1M v4
//     here); expected penalty ~4us vs ~10us serial savings.
__global__ void __launch_bounds__(256) edge_fused_kernel(
        const float* __restrict__ degrees,
        const float* __restrict__ maps,
        const int*   __restrict__ eidx32,
        float*       __restrict__ out,
        int E) {
    __shared__ float Asm[8][256];
    __shared__ float Bsm[8][256];
    __shared__ float Tsm[8][16][20];   // pad 20: float4-aligned rows

    const int tid  = threadIdx.x;
    const int w    = tid >> 5;         // edge slot 0..7 (one warp each)
    const int lane = tid & 31;
    const int e    = blockIdx.x * 8 + w;

    const int stride = idx_stride(eidx32);
    const int r = eidx32[(size_t)e * stride];
    const int c = eidx32[(size_t)(2 * E + e) * stride];

    // Stage both maps: 64 float4 per matrix, 2 per lane
    {
        const float4* ga = (const float4*)(maps + (size_t)e * 256);
        const float4* gb = (const float4*)(maps + ((size_t)e + E) * 256);
        ((float4*)Asm[w])[lane]      = ga[lane];
        ((float4*)Asm[w])[lane + 32] = ga[lane + 32];
        ((float4*)Bsm[w])[lane]      = gb[lane];
        ((float4*)Bsm[w])[lane + 32] = gb[lane + 32];
    }
    __syncwarp();

    const int j = lane >> 2;           // row pair {j, j+8}, j in 0..7
    const int q = lane & 3;            // float4 column group 0..3

    float t00=0.f,t01=0.f,t02=0.f,t03=0.f, t10=0.f,t11=0.f,t12=0.f,t13=0.f;
    float p00=0.f,p01=0.f,p02=0.f,p03=0.f, p10=0.f,p11=0.f,p12=0.f,p13=0.f;
    float u00=0.f,u01=0.f,u02=0.f,u03=0.f, u10=0.f,u11=0.f,u12=0.f,u13=0.f;

    #pragma unroll
    for (int i = 0; i < 16; ++i) {
        const float  aj0 = Asm[w][i * 16 + j];         // broadcast
        const float  aj1 = Asm[w][i * 16 + j + 8];
        const float  bj0 = Bsm[w][i * 16 + j];
        const float  bj1 = Bsm[w][i * 16 + j + 8];
        const float4 a4  = *(const float4*)&Asm[w][i * 16 + q * 4];
        const float4 b4  = *(const float4*)&Bsm[w][i * 16 + q * 4];

        t00 += aj0*b4.x; t01 += aj0*b4.y; t02 += aj0*b4.z; t03 += aj0*b4.w;
        t10 += aj1*b4.x; t11 += aj1*b4.y; t12 += aj1*b4.z; t13 += aj1*b4.w;
        p00 += aj0*a4.x; p01 += aj0*a4.y; p02 += aj0*a4.z; p03 += aj0*a4.w;
        p10 += aj1*a4.x; p11 += aj1*a4.y; p12 += aj1*a4.z; p13 += aj1*a4.w;
        u00 += bj0*b4.x; u01 += bj0*b4.y; u02 += bj0*b4.z; u03 += bj0*b4.w;
        u10 += bj1*b4.x; u11 += bj1*b4.y; u12 += bj1*b4.z; u13 += bj1*b4.w;
    }

    const float dr = rsqrtf(degrees[r] * (float)D_DIM + 1.0f);
    const float dc = rsqrtf(degrees[c] * (float)D_DIM + 1.0f);
    const float s  = -(dr * dc);
    const float sr = dr * dr;
    const float sc = dc * dc;

    // Diagonal Gram contributions: 4 vector REDs per thread, straight into
    // out's diagonal blocks (r,r) and (c,c)
    float* dgr = &out[(size_t)(r * 16) * NM + r * 16];
    red_add_v4(&dgr[(size_t)j * NM + q * 4],
               sr * p00, sr * p01, sr * p02, sr * p03);
    red_add_v4(&dgr[(size_t)(j + 8) * NM + q * 4],
               sr * p10, sr * p11, sr * p12, sr * p13);

    float* dgc = &out[(size_t)(c * 16) * NM + c * 16];
    red_add_v4(&dgc[(size_t)j * NM + q * 4],
               sc * u00, sc * u01, sc * u02, sc * u03);
    red_add_v4(&dgc[(size_t)(j + 8) * NM + q * 4],
               sc * u10, sc * u11, sc * u12, sc * u13);

    // Triu block (r,c): straight from registers, coalesced float4
    float4 v0;  v0.x = s*t00;  v0.y = s*t01;  v0.z = s*t02;  v0.w = s*t03;
    float4 v1;  v1.x = s*t10;  v1.y = s*t11;  v1.z = s*t12;  v1.w = s*t13;
    *(float4*)&out[(size_t)(r * 16 + j)     * NM + c * 16 + q * 4] = v0;
    *(float4*)&out[(size_t)(r * 16 + j + 8) * NM + c * 16 + q * 4] = v1;

    // Tril block (c,r) = T^T: stage, warp-sync, transpose-read, float4 store
    *(float4*)&Tsm[w][j][q * 4]     = v0;
    *(float4*)&Tsm[w][j + 8][q * 4] = v1;
    __syncwarp();
    float4 w0, w1;
    w0.x = Tsm[w][q*4+0][j];     w0.y = Tsm[w][q*4+1][j];
    w0.z = Tsm[w][q*4+2][j];     w0.w = Tsm[w][q*4+3][j];
    w1.x = Tsm[w][q*4+0][j+8];   w1.y = Tsm[w][q*4+1][j+8];
    w1.z = Tsm[w][q*4+2][j+8];   w1.w = Tsm[w][q*4+3][j+8];
    *(float4*)&out[(size_t)(c * 16 + j)     * NM + r * 16 + q * 4] = w0;
    *(float4*)&out[(size_t)(c * 16 + j + 8) * NM + r * 16 + q * 4] = w1;
}

extern "C" void kernel_launch(void* const* d_in, const int* in_sizes, int n_in,
                              void* d_out, int out_size) {
    // Inputs (metadata order): adj_mat [N*N f32], degrees [N f32],
    // maps [2E*16*16 f32], edge_index [2*2E int]
    const float* degrees = (const float*)d_in[1];
    const float* maps    = (const float*)d_in[2];
    const int*   eidx32  = (const int*)d_in[3];
    float*       out     = (float*)d_out;

    const int E = in_sizes[2] / (2 * 256);   // maps has 2E blocks of 256 floats

    // 1) Pure bandwidth-optimal zero fill of the 1.07 GB output (serial:
    //    R5/R6 showed overlap with the big memset is net-negative)
    cudaMemsetAsync(d_out, 0, (size_t)out_size * sizeof(float), 0);

    // 2) Fused: warp-per-edge compute + direct triu/tril stores + v4-REDs
    //    into out's diagonal blocks. Two graph nodes total.
    edge_fused_kernel<<<E / 8, 256>>>(degrees, maps, eidx32, out, E);
}

// round 16
// speedup vs baseline: 1.0929x; 1.0008x over previous
#include <cuda_runtime.h>
#include <cstddef>

// Problem constants (fixed by the reference: N=1024, D=16, E=16384)
#define NNODES 1024
#define D_DIM  16
#define NM     16384          // N * D

// Inline edge_index dtype probe (deterministic single word):
// int32 layout (2,32768): word 32769 = edge_index[1][1] = col[1] >= 1 (r < c).
// int64 LE layout: word 32769 = high half of edge_index[0][16384] < 1024 -> 0.
__device__ __forceinline__ int idx_stride(const int* eidx32) {
    return (__ldg(&eidx32[32769]) != 0) ? 1 : 2;
}

// Vector reduction (sm_90+ PTX): one instruction per 16B of accumulation.
__device__ __forceinline__ void red_add_v4(float* ptr, float a, float b,
                                           float c, float d) {
    asm volatile("red.global.add.v4.f32 [%0], {%1, %2, %3, %4};"
                 :: "l"(ptr), "f"(a), "f"(b), "f"(c), "f"(d) : "memory");
}

// Fused pass: ONE WARP PER EDGE (8 edges per 256-thread CTA). Thread
// (j = lane>>2, q = lane&3) owns rows {j, j+8} x cols [4q, 4q+4) of
// T = A^T B, G1 = A^T A, G2 = B^T B: 6 LDS feed 24 FMAs per i-step.
// smem is POOLED per warp (2080B slice): A[0..255], B[256..511] during the
// compute loop; the same slice is reused as the 16x20 transpose tile after
// a __syncwarp (disjoint lifetimes). 27KB -> 16.6KB per CTA lifts the
// smem-capped occupancy from 8 to 13 CTAs/SM to hide LDS + RED latency.
//   - triu block (r,c): direct float4 stores from registers
//   - tril block (c,r): transpose through the reused padded smem slice
//   - diag Gram: red.v4 directly into out's diagonal blocks (R15: net win
//     vs scratch+flush; memset provides the zero initial value)
__global__ void __launch_bounds__(256) edge_fused_kernel(
        const float* __restrict__ degrees,
        const float* __restrict__ maps,
        const int*   __restrict__ eidx32,
        float*       __restrict__ out,
        int E) {
    __shared__ float pool[8][520];     // 520 floats = 2080B: 16B-aligned slices

    const int tid  = threadIdx.x;
    const int w    = tid >> 5;         // edge slot 0..7 (one warp each)
    const int lane = tid & 31;
    const int e    = blockIdx.x * 8 + w;

    float* Asm = &pool[w][0];          // A: 256 floats
    float* Bsm = &pool[w][256];        // B: 256 floats

    const int stride = idx_stride(eidx32);
    const int r = eidx32[(size_t)e * stride];
    const int c = eidx32[(size_t)(2 * E + e) * stride];

    // Stage both maps: 64 float4 per matrix, 2 per lane
    {
        const float4* ga = (const float4*)(maps + (size_t)e * 256);
        const float4* gb = (const float4*)(maps + ((size_t)e + E) * 256);
        ((float4*)Asm)[lane]      = ga[lane];
        ((float4*)Asm)[lane + 32] = ga[lane + 32];
        ((float4*)Bsm)[lane]      = gb[lane];
        ((float4*)Bsm)[lane + 32] = gb[lane + 32];
    }
    __syncwarp();

    const int j = lane >> 2;           // row pair {j, j+8}, j in 0..7
    const int q = lane & 3;            // float4 column group 0..3

    float t00=0.f,t01=0.f,t02=0.f,t03=0.f, t10=0.f,t11=0.f,t12=0.f,t13=0.f;
    float p00=0.f,p01=0.f,p02=0.f,p03=0.f, p10=0.f,p11=0.f,p12=0.f,p13=0.f;
    float u00=0.f,u01=0.f,u02=0.f,u03=0.f, u10=0.f,u11=0.f,u12=0.f,u13=0.f;

    #pragma unroll
    for (int i = 0; i < 16; ++i) {
        const float  aj0 = Asm[i * 16 + j];            // broadcast
        const float  aj1 = Asm[i * 16 + j + 8];
        const float  bj0 = Bsm[i * 16 + j];
        const float  bj1 = Bsm[i * 16 + j + 8];
        const float4 a4  = *(const float4*)&Asm[i * 16 + q * 4];
        const float4 b4  = *(const float4*)&Bsm[i * 16 + q * 4];

        t00 += aj0*b4.x; t01 += aj0*b4.y; t02 += aj0*b4.z; t03 += aj0*b4.w;
        t10 += aj1*b4.x; t11 += aj1*b4.y; t12 += aj1*b4.z; t13 += aj1*b4.w;
        p00 += aj0*a4.x; p01 += aj0*a4.y; p02 += aj0*a4.z; p03 += aj0*a4.w;
        p10 += aj1*a4.x; p11 += aj1*a4.y; p12 += aj1*a4.z; p13 += aj1*a4.w;
        u00 += bj0*b4.x; u01 += bj0*b4.y; u02 += bj0*b4.z; u03 += bj0*b4.w;
        u10 += bj1*b4.x; u11 += bj1*b4.y; u12 += bj1*b4.z; u13 += bj1*b4.w;
    }

    const float dr = rsqrtf(degrees[r] * (float)D_DIM + 1.0f);
    const float dc = rsqrtf(degrees[c] * (float)D_DIM + 1.0f);
    const float s  = -(dr * dc);
    const float sr = dr * dr;
    const float sc = dc * dc;

    // Diagonal Gram contributions: 4 vector REDs per thread, straight into
    // out's diagonal blocks (r,r) and (c,c)
    float* dgr = &out[(size_t)(r * 16) * NM + r * 16];
    red_add_v4(&dgr[(size_t)j * NM + q * 4],
               sr * p00, sr * p01, sr * p02, sr * p03);
    red_add_v4(&dgr[(size_t)(j + 8) * NM + q * 4],
               sr * p10, sr * p11, sr * p12, sr * p13);

    float* dgc = &out[(size_t)(c * 16) * NM + c * 16];
    red_add_v4(&dgc[(size_t)j * NM + q * 4],
               sc * u00, sc * u01, sc * u02, sc * u03);
    red_add_v4(&dgc[(size_t)(j + 8) * NM + q * 4],
               sc * u10, sc * u11, sc * u12, sc * u13);

    // Triu block (r,c): straight from registers, coalesced float4
    float4 v0;  v0.x = s*t00;  v0.y = s*t01;  v0.z = s*t02;  v0.w = s*t03;
    float4 v1;  v1.x = s*t10;  v1.y = s*t11;  v1.z = s*t12;  v1.w = s*t13;
    *(float4*)&out[(size_t)(r * 16 + j)     * NM + c * 16 + q * 4] = v0;
    *(float4*)&out[(size_t)(r * 16 + j + 8) * NM + c * 16 + q * 4] = v1;

    // Tril block (c,r) = T^T: REUSE this warp's pool slice as a 16x20 tile
    // (all loop reads of Asm/Bsm retired by this __syncwarp)
    __syncwarp();
    float (*Tsm)[20] = (float (*)[20]) & pool[w][0];   // 320 floats < 512
    *(float4*)&Tsm[j][q * 4]     = v0;
    *(float4*)&Tsm[j + 8][q * 4] = v1;
    __syncwarp();
    float4 w0, w1;
    w0.x = Tsm[q*4+0][j];     w0.y = Tsm[q*4+1][j];
    w0.z = Tsm[q*4+2][j];     w0.w = Tsm[q*4+3][j];
    w1.x = Tsm[q*4+0][j+8];   w1.y = Tsm[q*4+1][j+8];
    w1.z = Tsm[q*4+2][j+8];   w1.w = Tsm[q*4+3][j+8];
    *(float4*)&out[(size_t)(c * 16 + j)     * NM + r * 16 + q * 4] = w0;
    *(float4*)&out[(size_t)(c * 16 + j + 8) * NM + r * 16 + q * 4] = w1;
}

extern "C" void kernel_launch(void* const* d_in, const int* in_sizes, int n_in,
                              void* d_out, int out_size) {
    // Inputs (metadata order): adj_mat [N*N f32], degrees [N f32],
    // maps [2E*16*16 f32], edge_index [2*2E int]
    const float* degrees = (const float*)d_in[1];
    const float* maps    = (const float*)d_in[2];
    const int*   eidx32  = (const int*)d_in[3];
    float*       out     = (float*)d_out;

    const int E = in_sizes[2] / (2 * 256);   // maps has 2E blocks of 256 floats

    // 1) Pure bandwidth-optimal zero fill of the 1.07 GB output (serial:
    //    R5/R6 showed overlap with the big memset is net-negative)
    cudaMemsetAsync(d_out, 0, (size_t)out_size * sizeof(float), 0);

    // 2) Fused: warp-per-edge compute + direct triu/tril stores + v4-REDs
    //    into out's diagonal blocks. Two graph nodes total.
    edge_fused_kernel<<<E / 8, 256>>>(degrees, maps, eidx32, out, E);
}

// round 17
// speedup vs baseline: 1.0955x; 1.0023x over previous
#include <cuda_runtime.h>
#include <cstddef>

// Problem constants (fixed by the reference: N=1024, D=16, E=16384)
#define NNODES 1024
#define D_DIM  16
#define NM     16384          // N * D

// Inline edge_index dtype probe (deterministic single word):
// int32 layout (2,32768): word 32769 = edge_index[1][1] = col[1] >= 1 (r < c).
// int64 LE layout: word 32769 = high half of edge_index[0][16384] < 1024 -> 0.
__device__ __forceinline__ int idx_stride(const int* eidx32) {
    return (__ldg(&eidx32[32769]) != 0) ? 1 : 2;
}

// Vector reduction (sm_90+ PTX): one instruction per 16B of accumulation.
__device__ __forceinline__ void red_add_v4(float* ptr, float a, float b,
                                           float c, float d) {
    asm volatile("red.global.add.v4.f32 [%0], {%1, %2, %3, %4};"
                 :: "l"(ptr), "f"(a), "f"(b), "f"(c), "f"(d) : "memory");
}

// Fused pass: ONE WARP PER EDGE, 4 edges per 128-thread CTA.
// CTA shrunk from 256 to 128 threads purely for occupancy packaging: at
// 56 regs/thread the register file fits 9x128-thread CTAs per SM (1152
// threads, ~56% occ) vs 4x256 (1024, 43%) — more resident warps for this
// latency-bound kernel with an unchanged per-warp instruction stream.
// Thread (j = lane>>2, q = lane&3) owns rows {j, j+8} x cols [4q, 4q+4) of
// T = A^T B, G1 = A^T A, G2 = B^T B: 6 LDS feed 24 FMAs per i-step.
// smem pooled per warp (2080B): A[0..255], B[256..511] during compute,
// slice reused as the 16x20 transpose tile afterwards (disjoint lifetimes).
//   - triu block (r,c): direct float4 stores from registers
//   - tril block (c,r): transpose through the reused padded smem slice
//   - diag Gram: red.v4 directly into out's diagonal blocks (R15 net win;
//     memset provides the zero initial value)
__global__ void __launch_bounds__(128) edge_fused_kernel(
        const float* __restrict__ degrees,
        const float* __restrict__ maps,
        const int*   __restrict__ eidx32,
        float*       __restrict__ out,
        int E) {
    __shared__ float pool[4][520];     // 520 floats = 2080B: 16B-aligned slices

    const int tid  = threadIdx.x;
    const int w    = tid >> 5;         // edge slot 0..3 (one warp each)
    const int lane = tid & 31;
    const int e    = blockIdx.x * 4 + w;

    float* Asm = &pool[w][0];          // A: 256 floats
    float* Bsm = &pool[w][256];        // B: 256 floats

    const int stride = idx_stride(eidx32);
    const int r = eidx32[(size_t)e * stride];
    const int c = eidx32[(size_t)(2 * E + e) * stride];

    // Stage both maps: 64 float4 per matrix, 2 per lane
    {
        const float4* ga = (const float4*)(maps + (size_t)e * 256);
        const float4* gb = (const float4*)(maps + ((size_t)e + E) * 256);
        ((float4*)Asm)[lane]      = ga[lane];
        ((float4*)Asm)[lane + 32] = ga[lane + 32];
        ((float4*)Bsm)[lane]      = gb[lane];
        ((float4*)Bsm)[lane + 32] = gb[lane + 32];
    }
    __syncwarp();

    const int j = lane >> 2;           // row pair {j, j+8}, j in 0..7
    const int q = lane & 3;            // float4 column group 0..3

    float t00=0.f,t01=0.f,t02=0.f,t03=0.f, t10=0.f,t11=0.f,t12=0.f,t13=0.f;
    float p00=0.f,p01=0.f,p02=0.f,p03=0.f, p10=0.f,p11=0.f,p12=0.f,p13=0.f;
    float u00=0.f,u01=0.f,u02=0.f,u03=0.f, u10=0.f,u11=0.f,u12=0.f,u13=0.f;

    #pragma unroll
    for (int i = 0; i < 16; ++i) {
        const float  aj0 = Asm[i * 16 + j];            // broadcast
        const float  aj1 = Asm[i * 16 + j + 8];
        const float  bj0 = Bsm[i * 16 + j];
        const float  bj1 = Bsm[i * 16 + j + 8];
        const float4 a4  = *(const float4*)&Asm[i * 16 + q * 4];
        const float4 b4  = *(const float4*)&Bsm[i * 16 + q * 4];

        t00 += aj0*b4.x; t01 += aj0*b4.y; t02 += aj0*b4.z; t03 += aj0*b4.w;
        t10 += aj1*b4.x; t11 += aj1*b4.y; t12 += aj1*b4.z; t13 += aj1*b4.w;
        p00 += aj0*a4.x; p01 += aj0*a4.y; p02 += aj0*a4.z; p03 += aj0*a4.w;
        p10 += aj1*a4.x; p11 += aj1*a4.y; p12 += aj1*a4.z; p13 += aj1*a4.w;
        u00 += bj0*b4.x; u01 += bj0*b4.y; u02 += bj0*b4.z; u03 += bj0*b4.w;
        u10 += bj1*b4.x; u11 += bj1*b4.y; u12 += bj1*b4.z; u13 += bj1*b4.w;
    }

    const float dr = rsqrtf(degrees[r] * (float)D_DIM + 1.0f);
    const float dc = rsqrtf(degrees[c] * (float)D_DIM + 1.0f);
    const float s  = -(dr * dc);
    const float sr = dr * dr;
    const float sc = dc * dc;

    // Diagonal Gram contributions: 4 vector REDs per thread, straight into
    // out's diagonal blocks (r,r) and (c,c)
    float* dgr = &out[(size_t)(r * 16) * NM + r * 16];
    red_add_v4(&dgr[(size_t)j * NM + q * 4],
               sr * p00, sr * p01, sr * p02, sr * p03);
    red_add_v4(&dgr[(size_t)(j + 8) * NM + q * 4],
               sr * p10, sr * p11, sr * p12, sr * p13);

    float* dgc = &out[(size_t)(c * 16) * NM + c * 16];
    red_add_v4(&dgc[(size_t)j * NM + q * 4],
               sc * u00, sc * u01, sc * u02, sc * u03);
    red_add_v4(&dgc[(size_t)(j + 8) * NM + q * 4],
               sc * u10, sc * u11, sc * u12, sc * u13);

    // Triu block (r,c): straight from registers, coalesced float4
    float4 v0;  v0.x = s*t00;  v0.y = s*t01;  v0.z = s*t02;  v0.w = s*t03;
    float4 v1;  v1.x = s*t10;  v1.y = s*t11;  v1.z = s*t12;  v1.w = s*t13;
    *(float4*)&out[(size_t)(r * 16 + j)     * NM + c * 16 + q * 4] = v0;
    *(float4*)&out[(size_t)(r * 16 + j + 8) * NM + c * 16 + q * 4] = v1;

    // Tril block (c,r) = T^T: REUSE this warp's pool slice as a 16x20 tile
    // (all loop reads of Asm/Bsm retired by this __syncwarp)
    __syncwarp();
    float (*Tsm)[20] = (float (*)[20]) & pool[w][0];   // 320 floats < 520
    *(float4*)&Tsm[j][q * 4]     = v0;
    *(float4*)&Tsm[j + 8][q * 4] = v1;
    __syncwarp();
    float4 w0, w1;
    w0.x = Tsm[q*4+0][j];     w0.y = Tsm[q*4+1][j];
    w0.z = Tsm[q*4+2][j];     w0.w = Tsm[q*4+3][j];
    w1.x = Tsm[q*4+0][j+8];   w1.y = Tsm[q*4+1][j+8];
    w1.z = Tsm[q*4+2][j+8];   w1.w = Tsm[q*4+3][j+8];
    *(float4*)&out[(size_t)(c * 16 + j)     * NM + r * 16 + q * 4] = w0;
    *(float4*)&out[(size_t)(c * 16 + j + 8) * NM + r * 16 + q * 4] = w1;
}

extern "C" void kernel_launch(void* const* d_in, const int* in_sizes, int n_in,
                              void* d_out, int out_size) {
    // Inputs (metadata order): adj_mat [N*N f32], degrees [N f32],
    // maps [2E*16*16 f32], edge_index [2*2E int]
    const float* degrees = (const float*)d_in[1];
    const float* maps    = (const float*)d_in[2];
    const int*   eidx32  = (const int*)d_in[3];
    float*       out     = (float*)d_out;

    const int E = in_sizes[2] / (2 * 256);   // maps has 2E blocks of 256 floats

    // 1) Pure bandwidth-optimal zero fill of the 1.07 GB output (serial:
    //    R5/R6 showed overlap with the big memset is net-negative)
    cudaMemsetAsync(d_out, 0, (size_t)out_size * sizeof(float), 0);

    // 2) Fused: warp-per-edge compute + direct triu/tril stores + v4-REDs
    //    into out's diagonal blocks. Two graph nodes total.
    edge_fused_kernel<<<E / 4, 128>>>(degrees, maps, eidx32, out, E);
}